// round 15
// baseline (speedup 1.0000x reference)
#include <cuda_runtime.h>

// Elementwise CGP model — R8 champion config, TPB=512 geometry test.
//   n7 = __sinf(x0*x1 + c0) * (x2*x3) + __sinf(x2)
//   n8 = __cosf(n7)*c1 + x0
//
// Identical per-thread work, coalescing, and cache policy to the confirmed
// 29.15/29.18us champion; only change: 512 threads/block (2048 rows/block,
// interleave stride 512), halving CTA count 8192 -> 4096.
//  - __ldcs float4 loads, 16B lane stride, MLP=4
//  - default-policy float2 stores (output stays L2-resident across replays)

__device__ __forceinline__ float2 cgp_row(float4 x, float c0, float c1) {
    float n4 = __fmaf_rn(x.x, x.y, c0);
    float n5 = __sinf(n4);
    float n6 = x.z * x.w;
    float n7 = __fmaf_rn(n5, n6, __sinf(x.z));
    float n8 = __fmaf_rn(__cosf(n7), c1, x.x);
    return make_float2(n7, n8);
}

__global__ void __launch_bounds__(512, 4)
cgp_kernel(const float4* __restrict__ X,
           const float* __restrict__ ephs,
           float2* __restrict__ out) {
    const int base = blockIdx.x * 2048 + threadIdx.x;

    const float c0 = __ldg(&ephs[0]);
    const float c1 = __ldg(&ephs[1]);

    // Front-batched coalesced streaming loads, MLP=4.
    float4 a = __ldcs(&X[base + 0 * 512]);
    float4 b = __ldcs(&X[base + 1 * 512]);
    float4 c = __ldcs(&X[base + 2 * 512]);
    float4 d = __ldcs(&X[base + 3 * 512]);

    // Default-policy stores: output claims/keeps L2 residency.
    out[base + 0 * 512] = cgp_row(a, c0, c1);
    out[base + 1 * 512] = cgp_row(b, c0, c1);
    out[base + 2 * 512] = cgp_row(c, c0, c1);
    out[base + 3 * 512] = cgp_row(d, c0, c1);
}

extern "C" void kernel_launch(void* const* d_in, const int* in_sizes, int n_in,
                              void* d_out, int out_size) {
    const float4* X   = (const float4*)d_in[0];   // (B, 4) float32, one float4/row
    const float*  eph = (const float*)d_in[1];    // (2,)   float32
    float2*       out = (float2*)d_out;           // (B, 2) float32, one float2/row

    int B = in_sizes[0] / 4;       // rows = 8388608
    int blocks = B / 2048;         // 2048 rows per block (B divisible) -> 4096

    cgp_kernel<<<blocks, 512>>>(X, eph, out);
}